// round 1
// baseline (speedup 1.0000x reference)
#include <cuda_runtime.h>
#include <math.h>

#define B_  8
#define N_  4096
#define KNN 5
#define ALPHA 1.05f

// Scratch (no device allocations allowed)
__device__ float g_value[B_ * N_];
__device__ float g_loss[B_];

// ---------------------------------------------------------------------------
// Kernel 1: per-point mean kNN (k=5) squared distance.
// One block handles 128 query points of one batch; the whole batch point
// cloud (4096 pts) is staged in shared memory (48 KB) and scanned by every
// thread with a register-resident sorted top-6 (includes self-dist 0, which
// occupies slot 0 and is dropped — matching the reference's "drop smallest").
// ---------------------------------------------------------------------------
__global__ __launch_bounds__(128) void knn_value_kernel(const float* __restrict__ pc)
{
    __shared__ float sx[N_];
    __shared__ float sy[N_];
    __shared__ float sz[N_];

    const int b = blockIdx.y;
    const float* __restrict__ p = pc + (size_t)b * N_ * 3;

    // Coalesced stage of [4096,3] into SoA shared arrays.
    for (int idx = threadIdx.x; idx < 3 * N_; idx += blockDim.x) {
        float v = __ldg(p + idx);
        int pt = idx / 3;
        int c  = idx - pt * 3;
        if (c == 0)      sx[pt] = v;
        else if (c == 1) sy[pt] = v;
        else             sz[pt] = v;
    }
    __syncthreads();

    const int i = blockIdx.x * blockDim.x + threadIdx.x;
    const float xi = sx[i];
    const float yi = sy[i];
    const float zi = sz[i];

    const float INF = __int_as_float(0x7f800000);
    float b0 = INF, b1 = INF, b2 = INF, b3 = INF, b4 = INF, b5 = INF;

#pragma unroll 8
    for (int j = 0; j < N_; ++j) {
        float dx = xi - sx[j];
        float dy = yi - sy[j];
        float dz = zi - sz[j];
        float d  = fmaf(dx, dx, fmaf(dy, dy, dz * dz));
        if (d < b5) {
            b5 = d;
            float t;
            t = fminf(b4, b5); b5 = fmaxf(b4, b5); b4 = t;
            t = fminf(b3, b4); b4 = fmaxf(b3, b4); b3 = t;
            t = fminf(b2, b3); b3 = fmaxf(b2, b3); b2 = t;
            t = fminf(b1, b2); b2 = fmaxf(b1, b2); b1 = t;
            t = fminf(b0, b1); b1 = fmaxf(b0, b1); b0 = t;
        }
    }

    // Drop the smallest (self / slot 0), mean of the next 5.
    g_value[b * N_ + i] = (b1 + b2 + b3 + b4 + b5) * 0.2f;
}

// ---------------------------------------------------------------------------
// Kernel 2: per-batch mean/std(ddof=1) -> threshold -> masked mean * weight.
// ---------------------------------------------------------------------------
__global__ __launch_bounds__(512) void batch_loss_kernel(const float* __restrict__ weights)
{
    const int b = blockIdx.x;
    const float* __restrict__ v = g_value + b * N_;
    const int tid = threadIdx.x;

    __shared__ float sh_a[16];
    __shared__ float sh_b[16];
    __shared__ float sh_thr;

    // Pass 1: sum and sum of squares.
    float s = 0.f, s2 = 0.f;
    for (int t = tid; t < N_; t += 512) {
        float x = v[t];
        s  += x;
        s2 = fmaf(x, x, s2);
    }
#pragma unroll
    for (int o = 16; o > 0; o >>= 1) {
        s  += __shfl_down_sync(0xffffffffu, s,  o);
        s2 += __shfl_down_sync(0xffffffffu, s2, o);
    }
    if ((tid & 31) == 0) { sh_a[tid >> 5] = s; sh_b[tid >> 5] = s2; }
    __syncthreads();
    if (tid < 32) {
        s  = (tid < 16) ? sh_a[tid] : 0.f;
        s2 = (tid < 16) ? sh_b[tid] : 0.f;
#pragma unroll
        for (int o = 8; o > 0; o >>= 1) {
            s  += __shfl_down_sync(0xffffffffu, s,  o);
            s2 += __shfl_down_sync(0xffffffffu, s2, o);
        }
        if (tid == 0) {
            float mean = s / (float)N_;
            float var  = (s2 - s * s / (float)N_) / (float)(N_ - 1);
            var = fmaxf(var, 0.f);
            sh_thr = mean + ALPHA * sqrtf(var);
        }
    }
    __syncthreads();

    // Pass 2: masked sum (mask = value > threshold).
    const float thr = sh_thr;
    float m = 0.f;
    for (int t = tid; t < N_; t += 512) {
        float x = v[t];
        if (x > thr) m += x;
    }
#pragma unroll
    for (int o = 16; o > 0; o >>= 1)
        m += __shfl_down_sync(0xffffffffu, m, o);
    if ((tid & 31) == 0) sh_a[tid >> 5] = m;
    __syncthreads();
    if (tid < 32) {
        m = (tid < 16) ? sh_a[tid] : 0.f;
#pragma unroll
        for (int o = 8; o > 0; o >>= 1)
            m += __shfl_down_sync(0xffffffffu, m, o);
        if (tid == 0)
            g_loss[b] = (m / (float)N_) * __ldg(weights + b);
    }
}

// ---------------------------------------------------------------------------
// Kernel 3: mean over batches -> scalar output.
// ---------------------------------------------------------------------------
__global__ void final_kernel(float* __restrict__ out)
{
    float s = 0.f;
#pragma unroll
    for (int b = 0; b < B_; ++b) s += g_loss[b];
    out[0] = s / (float)B_;
}

extern "C" void kernel_launch(void* const* d_in, const int* in_sizes, int n_in,
                              void* d_out, int out_size)
{
    const float* pc      = (const float*)d_in[0];  // [8, 4096, 3] f32
    const float* weights = (const float*)d_in[1];  // [8] f32
    float* out = (float*)d_out;

    dim3 grid1(N_ / 128, B_);
    knn_value_kernel<<<grid1, 128>>>(pc);
    batch_loss_kernel<<<B_, 512>>>(weights);
    final_kernel<<<1, 1>>>(out);
}

// round 2
// speedup vs baseline: 1.3789x; 1.3789x over previous
#include <cuda_runtime.h>
#include <math.h>

#define B_     8
#define N_     4096
#define ALPHA  1.05f
#define JC     4              // j-dimension split factor
#define JCHUNK (N_ / JC)      // 1024 candidates per block

// Scratch (no device allocations allowed)
__device__ float g_part[B_ * N_ * JC * 6];  // partial sorted top-6 per (b, i, chunk)
__device__ float g_loss[B_];

// ---------------------------------------------------------------------------
// Kernel 1: partial kNN. Each block scans one 1024-point j-chunk for 128
// query points, maintaining a register-resident sorted top-6 (ascending).
// Smem holds the chunk as float4 so the hot loop does ONE LDS.128 broadcast
// per candidate instead of three LDS.32.
// ---------------------------------------------------------------------------
__global__ __launch_bounds__(128) void knn_part_kernel(const float* __restrict__ pc)
{
    __shared__ float4 sp[JCHUNK];   // 16 KB

    const int b  = blockIdx.z;
    const int jc = blockIdx.y;
    const float* __restrict__ p = pc + (size_t)b * N_ * 3;

    // Stage chunk [jc*1024, (jc+1)*1024) as float4 {x,y,z,0}.
    const float* __restrict__ pj = p + (size_t)jc * JCHUNK * 3;
    for (int idx = threadIdx.x; idx < JCHUNK; idx += 128) {
        sp[idx] = make_float4(__ldg(pj + idx * 3),
                              __ldg(pj + idx * 3 + 1),
                              __ldg(pj + idx * 3 + 2), 0.f);
    }
    __syncthreads();

    const int i = blockIdx.x * 128 + threadIdx.x;
    const float xi = __ldg(p + i * 3);
    const float yi = __ldg(p + i * 3 + 1);
    const float zi = __ldg(p + i * 3 + 2);

    const float INF = __int_as_float(0x7f800000);
    float b0 = INF, b1 = INF, b2 = INF, b3 = INF, b4 = INF, b5 = INF;

#pragma unroll 8
    for (int j = 0; j < JCHUNK; ++j) {
        float4 q = sp[j];
        float dx = xi - q.x;
        float dy = yi - q.y;
        float dz = zi - q.z;
        float d  = fmaf(dx, dx, fmaf(dy, dy, dz * dz));
        if (d < b5) {
            b5 = d;
            float t;
            t = fminf(b4, b5); b5 = fmaxf(b4, b5); b4 = t;
            t = fminf(b3, b4); b4 = fmaxf(b3, b4); b3 = t;
            t = fminf(b2, b3); b3 = fmaxf(b2, b3); b2 = t;
            t = fminf(b1, b2); b2 = fmaxf(b1, b2); b1 = t;
            t = fminf(b0, b1); b1 = fmaxf(b0, b1); b0 = t;
        }
    }

    float* __restrict__ out = g_part + (((size_t)b * N_ + i) * JC + jc) * 6;
    out[0] = b0; out[1] = b1; out[2] = b2;
    out[3] = b3; out[4] = b4; out[5] = b5;
}

// ---------------------------------------------------------------------------
// Kernel 2 (fused): merge partial top-6 lists -> per-point value ->
// per-batch mean/std(ddof=1) -> threshold -> masked mean * weight.
// ---------------------------------------------------------------------------
__global__ __launch_bounds__(512) void loss_kernel(const float* __restrict__ weights)
{
    const int b   = blockIdx.x;
    const int tid = threadIdx.x;

    __shared__ float sval[N_];      // 16 KB per-point values
    __shared__ float sh_a[16];
    __shared__ float sh_b[16];
    __shared__ float sh_thr;

    const float INF = __int_as_float(0x7f800000);

    // Merge: global top-6 = 6 smallest of the 24 partial candidates.
    for (int pt = tid; pt < N_; pt += 512) {
        const float* __restrict__ part = g_part + ((size_t)b * N_ + pt) * (JC * 6);
        float c0 = INF, c1 = INF, c2 = INF, c3 = INF, c4 = INF, c5 = INF;
#pragma unroll
        for (int t = 0; t < JC * 6; ++t) {
            float d = part[t];
            if (d < c5) {
                c5 = d;
                float u;
                u = fminf(c4, c5); c5 = fmaxf(c4, c5); c4 = u;
                u = fminf(c3, c4); c4 = fmaxf(c3, c4); c3 = u;
                u = fminf(c2, c3); c3 = fmaxf(c2, c3); c2 = u;
                u = fminf(c1, c2); c2 = fmaxf(c1, c2); c1 = u;
                u = fminf(c0, c1); c1 = fmaxf(c0, c1); c0 = u;
            }
        }
        // Drop the smallest (self-distance), mean of the next 5.
        sval[pt] = (c1 + c2 + c3 + c4 + c5) * 0.2f;
    }
    __syncthreads();

    // Pass 1: sum and sum of squares over sval.
    float s = 0.f, s2 = 0.f;
    for (int t = tid; t < N_; t += 512) {
        float x = sval[t];
        s  += x;
        s2 = fmaf(x, x, s2);
    }
#pragma unroll
    for (int o = 16; o > 0; o >>= 1) {
        s  += __shfl_down_sync(0xffffffffu, s,  o);
        s2 += __shfl_down_sync(0xffffffffu, s2, o);
    }
    if ((tid & 31) == 0) { sh_a[tid >> 5] = s; sh_b[tid >> 5] = s2; }
    __syncthreads();
    if (tid < 32) {
        s  = (tid < 16) ? sh_a[tid] : 0.f;
        s2 = (tid < 16) ? sh_b[tid] : 0.f;
#pragma unroll
        for (int o = 8; o > 0; o >>= 1) {
            s  += __shfl_down_sync(0xffffffffu, s,  o);
            s2 += __shfl_down_sync(0xffffffffu, s2, o);
        }
        if (tid == 0) {
            float mean = s / (float)N_;
            float var  = (s2 - s * s / (float)N_) / (float)(N_ - 1);
            var = fmaxf(var, 0.f);
            sh_thr = mean + ALPHA * sqrtf(var);
        }
    }
    __syncthreads();

    // Pass 2: masked sum (value > threshold).
    const float thr = sh_thr;
    float m = 0.f;
    for (int t = tid; t < N_; t += 512) {
        float x = sval[t];
        if (x > thr) m += x;
    }
#pragma unroll
    for (int o = 16; o > 0; o >>= 1)
        m += __shfl_down_sync(0xffffffffu, m, o);
    if ((tid & 31) == 0) sh_a[tid >> 5] = m;
    __syncthreads();
    if (tid < 32) {
        m = (tid < 16) ? sh_a[tid] : 0.f;
#pragma unroll
        for (int o = 8; o > 0; o >>= 1)
            m += __shfl_down_sync(0xffffffffu, m, o);
        if (tid == 0)
            g_loss[b] = (m / (float)N_) * __ldg(weights + b);
    }
}

// ---------------------------------------------------------------------------
// Kernel 3: mean over batches -> scalar output.
// ---------------------------------------------------------------------------
__global__ void final_kernel(float* __restrict__ out)
{
    float s = 0.f;
#pragma unroll
    for (int b = 0; b < B_; ++b) s += g_loss[b];
    out[0] = s / (float)B_;
}

extern "C" void kernel_launch(void* const* d_in, const int* in_sizes, int n_in,
                              void* d_out, int out_size)
{
    const float* pc      = (const float*)d_in[0];  // [8, 4096, 3] f32
    const float* weights = (const float*)d_in[1];  // [8] f32
    float* out = (float*)d_out;

    dim3 grid1(N_ / 128, JC, B_);   // 32 x 4 x 8 = 1024 blocks
    knn_part_kernel<<<grid1, 128>>>(pc);
    loss_kernel<<<B_, 512>>>(weights);
    final_kernel<<<1, 1>>>(out);
}